// round 13
// baseline (speedup 1.0000x reference)
#include <cuda_runtime.h>
#include <cuda_fp16.h>
#include <math.h>
#include <stdint.h>

#define NEXP 32
#define KSEL 4
#define CAP  1280
#define NTOK 8192
#define DDIM 1024
#define IDIM 512

// phase1: M=256 tile, 512 threads, 3-stage
#define P1_THREADS 512
#define P1_A  32768                    // 256 rows x 64 fp16
#define P1_B  16384                    // 128 rows x 64 fp16
#define P1_BUF (P1_A + P1_B)
#define SMEM_P1 (3 * P1_BUF + 1024)
// phase2: M=128 tile, 256 threads, 3-stage
#define P2_THREADS 256
#define P2_T  16384
#define P2_BUF (2 * P2_T)
#define SMEM_P2 (3 * P2_BUF + 1024)

// ---------------- scratch (device globals; no allocation allowed) ----------
__device__ int   g_counts[NEXP];
__device__ int   g_row_token[NEXP * CAP];
__device__ int   g_tok_exp[NTOK * KSEL];
__device__ int   g_tok_pos[NTOK * KSEL];
__device__ float g_tok_w[NTOK * KSEL];

__device__ __half g_X [(size_t)NTOK * DDIM];
__device__ __half g_GU[(size_t)NEXP * 1024 * DDIM];   // gate/up row-interleaved
__device__ __half g_D [(size_t)NEXP * DDIM * IDIM];
__device__ __half g_H [(size_t)NEXP * CAP * IDIM];
__device__ __half g_Yh[(size_t)NEXP * CAP * DDIM];

// ---------------- PTX helpers (base compute_103 target only) ---------------
__device__ __forceinline__ uint32_t smem_u32(const void* p) {
    uint32_t a;
    asm("{ .reg .u64 t; cvta.to.shared.u64 t, %1; cvt.u32.u64 %0, t; }"
        : "=r"(a) : "l"(p));
    return a;
}
__device__ __forceinline__ void cp_async16(uint32_t dst, const void* src) {
    asm volatile("cp.async.cg.shared.global [%0], [%1], 16;"
                 :: "r"(dst), "l"(src));
}
#define CP_COMMIT() asm volatile("cp.async.commit_group;" ::: "memory")
#define CP_WAIT2()  asm volatile("cp.async.wait_group 2;" ::: "memory")
#define CP_WAIT1()  asm volatile("cp.async.wait_group 1;" ::: "memory")
#define CP_WAIT0()  asm volatile("cp.async.wait_group 0;" ::: "memory")

__device__ __forceinline__ void ldsm4(uint32_t* r, uint32_t a) {
    asm volatile("ldmatrix.sync.aligned.m8n8.x4.shared.b16 {%0,%1,%2,%3}, [%4];"
                 : "=r"(r[0]), "=r"(r[1]), "=r"(r[2]), "=r"(r[3]) : "r"(a));
}
__device__ __forceinline__ void mma_f16(float* c, const uint32_t* a,
                                        const uint32_t* b) {
    asm volatile(
        "mma.sync.aligned.m16n8k16.row.col.f32.f16.f16.f32 "
        "{%0,%1,%2,%3}, {%4,%5,%6,%7}, {%8,%9}, {%0,%1,%2,%3};"
        : "+f"(c[0]), "+f"(c[1]), "+f"(c[2]), "+f"(c[3])
        : "r"(a[0]), "r"(a[1]), "r"(a[2]), "r"(a[3]), "r"(b[0]), "r"(b[1]));
}

__device__ __forceinline__ uint32_t packh2(float a, float b) {
    __half2 h = __floats2half2_rn(a, b);
    return *reinterpret_cast<uint32_t*>(&h);
}

// ---------------- prep kernels ----------------------------------------------
__global__ void convert_gu_kernel(const float* __restrict__ gate_w,
                                  const float* __restrict__ up_w) {
    if (blockIdx.x == 0 && threadIdx.x < NEXP) g_counts[threadIdx.x] = 0;
    size_t u = (size_t)blockIdx.x * blockDim.x + threadIdx.x;
    if (u >= (size_t)NEXP * 1024 * DDIM / 8) return;
    size_t o = u * 8;
    size_t gr = o >> 10;
    int k = (int)(o & 1023);
    int e = (int)(gr >> 10);
    int r = (int)(gr & 1023);
    int i = r >> 1;
    const float* src = ((r & 1) ? up_w : gate_w) + ((size_t)e * IDIM + i) * DDIM + k;
    const float4* s4 = (const float4*)src;
    float4 v0 = s4[0], v1 = s4[1];
    ((uint4*)g_GU)[u] = make_uint4(packh2(v0.x, v0.y), packh2(v0.z, v0.w),
                                   packh2(v1.x, v1.y), packh2(v1.z, v1.w));
}

__global__ void convert_d_kernel(const float* __restrict__ down_w) {
    size_t u = (size_t)blockIdx.x * blockDim.x + threadIdx.x;
    if (u >= (size_t)NEXP * DDIM * IDIM / 8) return;
    const float4* s4 = (const float4*)down_w + u * 2;
    float4 v0 = s4[0], v1 = s4[1];
    ((uint4*)g_D)[u] = make_uint4(packh2(v0.x, v0.y), packh2(v0.z, v0.w),
                                  packh2(v1.x, v1.y), packh2(v1.z, v1.w));
}

// ---------------- router (also emits fp16 X) --------------------------------
__global__ void router_kernel(const float* __restrict__ x,
                              const float* __restrict__ rw,
                              float* __restrict__ logits_out) {
    __shared__ float xs[DDIM];
    __shared__ float lsh[NEXP];
    const int t = blockIdx.x;
    const int tid = threadIdx.x;

    const float4* xrow = (const float4*)(x + (size_t)t * DDIM);
    float4* xs4 = (float4*)xs;
    for (int i = tid; i < DDIM / 4; i += 128) xs4[i] = xrow[i];
    __syncthreads();

    {
        uint32_t* xo = (uint32_t*)(g_X + (size_t)t * DDIM);
#pragma unroll
        for (int j = 0; j < 4; j++) {
            int u = tid * 4 + j;
            xo[u] = packh2(xs[u * 2], xs[u * 2 + 1]);
        }
    }

    const int e = tid >> 2;
    const int s = tid & 3;
    const float4* w4 = (const float4*)(rw + e * DDIM + s * 256);
    const float4* a4 = (const float4*)(xs + s * 256);
    float acc = 0.f;
#pragma unroll 16
    for (int j = 0; j < 64; j++) {
        float4 a = a4[j], b = w4[j];
        acc += a.x * b.x + a.y * b.y + a.z * b.z + a.w * b.w;
    }
    acc += __shfl_xor_sync(0xffffffffu, acc, 1);
    acc += __shfl_xor_sync(0xffffffffu, acc, 2);
    if (s == 0) lsh[e] = acc;
    __syncthreads();

    if (tid < 32) {
        float lv = lsh[tid];
        if (logits_out) logits_out[(size_t)t * NEXP + tid] = lv;

        float cur = lv;
        float selv[KSEL];
        int   seli[KSEL];
#pragma unroll
        for (int k = 0; k < KSEL; k++) {
            float v = cur;
            int idx = tid;
#pragma unroll
            for (int off = 16; off; off >>= 1) {
                float ov = __shfl_xor_sync(0xffffffffu, v, off);
                int   oi = __shfl_xor_sync(0xffffffffu, idx, off);
                if (ov > v || (ov == v && oi < idx)) { v = ov; idx = oi; }
            }
            selv[k] = v;
            seli[k] = idx;
            if (tid == idx) cur = -3.4e38f;
        }

        if (tid < KSEL) {
            float m = selv[0];
            float sum = 0.f;
#pragma unroll
            for (int k = 0; k < KSEL; k++) sum += expf(selv[k] - m);
            float w = expf(selv[tid] - m) / sum;
            int   ex = seli[tid];
            int p = atomicAdd(&g_counts[ex], 1);
            int o = t * KSEL + tid;
            g_tok_exp[o] = ex;
            g_tok_pos[o] = p;
            g_tok_w[o]   = w;
            if (p < CAP) g_row_token[ex * CAP + p] = t;
        }
    }
}

__global__ void combine_kernel(float* __restrict__ out) {
    const int t = blockIdx.x;
    const int d = threadIdx.x * 4;
    float4 acc = make_float4(0.f, 0.f, 0.f, 0.f);
#pragma unroll
    for (int k = 0; k < KSEL; k++) {
        int o = t * KSEL + k;
        int e = g_tok_exp[o];
        int p = g_tok_pos[o];
        float w = g_tok_w[o];
        if (p < CAP) {
            const __half2* yp = (const __half2*)(g_Yh + ((size_t)e * CAP + p) * DDIM + d);
            float2 v0 = __half22float2(yp[0]);
            float2 v1 = __half22float2(yp[1]);
            acc.x += w * v0.x; acc.y += w * v0.y;
            acc.z += w * v1.x; acc.w += w * v1.y;
        }
    }
    *(float4*)&out[(size_t)t * DDIM + d] = acc;
}

// ---------------- GEMM phase 1: M=256 tile, 3-stage pipeline ----------------
__global__ __launch_bounds__(P1_THREADS)
void phase1_kernel() {
    extern __shared__ char smem[];
    const int e = blockIdx.z;
    const int cnt = min(g_counts[e], CAP);
    const int m0 = blockIdx.y * 256;
    if (m0 >= cnt) return;
    const int x0 = blockIdx.x;          // 64 i-values per tile
    const uint32_t sb = smem_u32(smem);
    int* tok_s = (int*)(smem + 3 * P1_BUF);

    const int tid = threadIdx.x;
    const int lane = tid & 31;
    const int wid = tid >> 5;
    const int wm = wid >> 1;            // 0..7
    const int wn = wid & 1;

    if (tid < 256) {
        int m = m0 + tid;
        tok_s[tid] = (m < cnt) ? g_row_token[e * CAP + m] : 0;
    }
    __syncthreads();

    int mytok[4];
#pragma unroll
    for (int it = 0; it < 4; it++) mytok[it] = tok_s[(tid >> 3) + 64 * it];
    const int myl = tid & 7;

    const size_t bbase = ((size_t)e * 1024 + x0 * 128) * DDIM;

    auto load_chunk = [&](int buf, int c) {
        uint32_t s = sb + buf * P1_BUF;
        int kk = c * 64;
#pragma unroll
        for (int it = 0; it < 4; it++) {             // A: 256 rows
            int row = (tid >> 3) + 64 * it;
            uint32_t dst = s + row * 128 + ((myl ^ (row & 7)) << 4);
            cp_async16(dst, g_X + (size_t)mytok[it] * DDIM + kk + myl * 8);
        }
#pragma unroll
        for (int it = 0; it < 2; it++) {             // B: 128 rows
            int row = (tid >> 3) + 64 * it;
            uint32_t dst = s + P1_A + row * 128 + ((myl ^ (row & 7)) << 4);
            cp_async16(dst, g_GU + bbase + (size_t)row * DDIM + kk + myl * 8);
        }
    };

    float acc[2][8][4] = {};
    const int g = lane >> 3;
    const int ar_off = (lane & 7) + (g & 1) * 8;
    const int ac_off = g >> 1;
    const int br_off = (lane & 7) + (g >> 1) * 8;
    const int bc_off = g & 1;

    load_chunk(0, 0); CP_COMMIT();
    load_chunk(1, 1); CP_COMMIT();
    int buf = 0;
    for (int c = 0; c < 16; c++) {
        if (c + 2 < 16) {
            int nb = buf + 2; if (nb >= 3) nb -= 3;
            load_chunk(nb, c + 2); CP_COMMIT(); CP_WAIT2();
        } else if (c + 1 < 16) CP_WAIT1();
        else CP_WAIT0();
        __syncthreads();
        uint32_t s = sb + buf * P1_BUF;
#pragma unroll
        for (int h = 0; h < 4; h++) {
            uint32_t ah[2][4], bb[4][4];
#pragma unroll
            for (int t = 0; t < 2; t++) {
                int r = wm * 32 + t * 16 + ar_off;
                int cc = h * 2 + ac_off;
                ldsm4(ah[t], s + r * 128 + ((cc ^ (r & 7)) << 4));
            }
#pragma unroll
            for (int j2 = 0; j2 < 4; j2++) {
                int n = wn * 64 + j2 * 16 + br_off;
                int cc = h * 2 + bc_off;
                ldsm4(bb[j2], s + P1_A + n * 128 + ((cc ^ (n & 7)) << 4));
            }
#pragma unroll
            for (int t = 0; t < 2; t++)
#pragma unroll
                for (int j = 0; j < 8; j++)
                    mma_f16(acc[t][j], ah[t], &bb[j >> 1][(j & 1) * 2]);
        }
        __syncthreads();
        if (++buf == 3) buf = 0;
    }

    // epilogue: c0 = gate_i, c1 = up_i (row-interleaved B) -> h = silu(g)*u
#pragma unroll
    for (int t = 0; t < 2; t++)
#pragma unroll
        for (int rh = 0; rh < 2; rh++) {
            int m = m0 + wm * 32 + t * 16 + rh * 8 + (lane >> 2);
            if (m < cnt) {
                size_t base = ((size_t)e * CAP + m) * IDIM + x0 * 64 + wn * 32 + (lane & 3);
#pragma unroll
                for (int j = 0; j < 8; j++) {
                    float gg = acc[t][j][rh * 2];
                    float uu = acc[t][j][rh * 2 + 1];
                    float hh = gg * (1.f / (1.f + expf(-gg))) * uu;
                    g_H[base + j * 4] = __float2half_rn(hh);
                }
            }
        }
}

// ---------------- GEMM phase 2: M=128 tile, 256 thr, 3-stage, fp16 out -----
__global__ __launch_bounds__(P2_THREADS)
void phase2_kernel() {
    extern __shared__ char smem[];
    const int e = blockIdx.z;
    const int cnt = min(g_counts[e], CAP);
    const int m0 = blockIdx.y * 128;
    if (m0 >= cnt) return;
    const int d0 = blockIdx.x * 128;
    const uint32_t sb = smem_u32(smem);

    const int tid = threadIdx.x;
    const int lane = tid & 31;
    const int wid = tid >> 5;
    const int wm = wid >> 1;
    const int wn = wid & 1;
    const int mycc = tid & 7;

    const size_t abase = ((size_t)e * CAP + m0) * IDIM;
    const size_t bbase = ((size_t)e * DDIM + d0) * IDIM;

    auto load_chunk = [&](int buf, int c) {
        uint32_t s = sb + buf * P2_BUF;
        int kk = c * 64;
#pragma unroll
        for (int it = 0; it < 4; it++) {
            int row = (tid >> 3) + 32 * it;
            uint32_t dst = s + row * 128 + ((mycc ^ (row & 7)) << 4);
            cp_async16(dst,         g_H + abase + (size_t)row * IDIM + kk + mycc * 8);
            cp_async16(dst + P2_T,  g_D + bbase + (size_t)row * IDIM + kk + mycc * 8);
        }
    };

    float acc[2][8][4] = {};
    const int g = lane >> 3;
    const int ar_off = (lane & 7) + (g & 1) * 8;
    const int ac_off = g >> 1;
    const int br_off = (lane & 7) + (g >> 1) * 8;
    const int bc_off = g & 1;

    load_chunk(0, 0); CP_COMMIT();
    load_chunk(1, 1); CP_COMMIT();
    int buf = 0;
    for (int c = 0; c < 8; c++) {
        if (c + 2 < 8) {
            int nb = buf + 2; if (nb >= 3) nb -= 3;
            load_chunk(nb, c + 2); CP_COMMIT(); CP_WAIT2();
        } else if (c + 1 < 8) CP_WAIT1();
        else CP_WAIT0();
        __syncthreads();
        uint32_t s = sb + buf * P2_BUF;
#pragma unroll
        for (int h = 0; h < 4; h++) {
            uint32_t ah[2][4], bb[4][4];
#pragma unroll
            for (int t = 0; t < 2; t++) {
                int r = wm * 32 + t * 16 + ar_off;
                int cc = h * 2 + ac_off;
                ldsm4(ah[t], s + r * 128 + ((cc ^ (r & 7)) << 4));
            }
#pragma unroll
            for (int j2 = 0; j2 < 4; j2++) {
                int n = wn * 64 + j2 * 16 + br_off;
                int cc = h * 2 + bc_off;
                ldsm4(bb[j2], s + P2_T + n * 128 + ((cc ^ (n & 7)) << 4));
            }
#pragma unroll
            for (int t = 0; t < 2; t++)
#pragma unroll
                for (int j = 0; j < 8; j++)
                    mma_f16(acc[t][j], ah[t], &bb[j >> 1][(j & 1) * 2]);
        }
        __syncthreads();
        if (++buf == 3) buf = 0;
    }

#pragma unroll
    for (int t = 0; t < 2; t++)
#pragma unroll
        for (int rh = 0; rh < 2; rh++) {
            int m = m0 + wm * 32 + t * 16 + rh * 8 + (lane >> 2);
            if (m < cnt) {
                __half* yp = g_Yh + ((size_t)e * CAP + m) * DDIM
                           + d0 + wn * 64 + (lane & 3) * 2;
#pragma unroll
                for (int j = 0; j < 8; j++) {
                    *(uint32_t*)(yp + j * 8) =
                        packh2(acc[t][j][rh * 2], acc[t][j][rh * 2 + 1]);
                }
            }
        }
}

// ---------------- host ------------------------------------------------------
extern "C" void kernel_launch(void* const* d_in, const int* in_sizes, int n_in,
                              void* d_out, int out_size) {
    const float* x  = (const float*)d_in[0];
    const float* rw = (const float*)d_in[1];
    const float* gw = (const float*)d_in[2];
    const float* uw = (const float*)d_in[3];
    const float* dw = (const float*)d_in[4];
    float* out = (float*)d_out;
    float* logits = (out_size >= NTOK * DDIM + NTOK * NEXP) ? (out + (size_t)NTOK * DDIM)
                                                            : nullptr;

    cudaFuncSetAttribute(phase1_kernel, cudaFuncAttributeMaxDynamicSharedMemorySize, SMEM_P1);
    cudaFuncSetAttribute(phase2_kernel, cudaFuncAttributeMaxDynamicSharedMemorySize, SMEM_P2);

    convert_gu_kernel<<<(NEXP * 1024 * DDIM / 8 + 255) / 256, 256>>>(gw, uw);
    convert_d_kernel<<<(NEXP * DDIM * IDIM / 8 + 255) / 256, 256>>>(dw);
    router_kernel<<<NTOK, 128>>>(x, rw, logits);
    phase1_kernel<<<dim3(IDIM / 64, CAP / 256, NEXP), P1_THREADS, SMEM_P1>>>();
    phase2_kernel<<<dim3(DDIM / 128, CAP / 128, NEXP), P2_THREADS, SMEM_P2>>>();
    combine_kernel<<<NTOK, 256>>>(out);
}

// round 16
// speedup vs baseline: 1.0323x; 1.0323x over previous
#include <cuda_runtime.h>
#include <cuda_fp16.h>
#include <math.h>
#include <stdint.h>

#define NEXP 32
#define KSEL 4
#define CAP  1280
#define NTOK 8192
#define DDIM 1024
#define IDIM 512

// phase1: M=256 tile, 512 threads, 3-stage
#define P1_THREADS 512
#define P1_A  32768                    // 256 rows x 64 fp16
#define P1_B  16384                    // 128 rows x 64 fp16
#define P1_BUF (P1_A + P1_B)
#define SMEM_P1 (3 * P1_BUF + 1024)
// phase2: M=128 tile, 256 threads, 2-stage (R11-proven config)
#define P2_THREADS 256
#define P2_T  16384
#define P2_BUF (2 * P2_T)
#define SMEM_P2 (2 * P2_BUF + 1024)

#define GU_BLOCKS (NEXP * 1024 * DDIM / 8 / 256)   // 16384
#define D_BLOCKS  (NEXP * DDIM * IDIM / 8 / 256)   // 8192

// ---------------- scratch (device globals; no allocation allowed) ----------
__device__ int   g_counts[NEXP];
__device__ int   g_row_token[NEXP * CAP];
__device__ int   g_tok_exp[NTOK * KSEL];
__device__ int   g_tok_pos[NTOK * KSEL];
__device__ float g_tok_w[NTOK * KSEL];

__device__ __half g_X [(size_t)NTOK * DDIM];
__device__ __half g_GU[(size_t)NEXP * 1024 * DDIM];   // gate/up row-interleaved
__device__ __half g_D [(size_t)NEXP * DDIM * IDIM];
__device__ __half g_H [(size_t)NEXP * CAP * IDIM];
__device__ __half g_Yh[(size_t)NEXP * CAP * DDIM];

// ---------------- PTX helpers (base compute_103 target only) ---------------
__device__ __forceinline__ uint32_t smem_u32(const void* p) {
    uint32_t a;
    asm("{ .reg .u64 t; cvta.to.shared.u64 t, %1; cvt.u32.u64 %0, t; }"
        : "=r"(a) : "l"(p));
    return a;
}
__device__ __forceinline__ void cp_async16(uint32_t dst, const void* src) {
    asm volatile("cp.async.cg.shared.global [%0], [%1], 16;"
                 :: "r"(dst), "l"(src));
}
#define CP_COMMIT() asm volatile("cp.async.commit_group;" ::: "memory")
#define CP_WAIT2()  asm volatile("cp.async.wait_group 2;" ::: "memory")
#define CP_WAIT1()  asm volatile("cp.async.wait_group 1;" ::: "memory")
#define CP_WAIT0()  asm volatile("cp.async.wait_group 0;" ::: "memory")

__device__ __forceinline__ void ldsm4(uint32_t* r, uint32_t a) {
    asm volatile("ldmatrix.sync.aligned.m8n8.x4.shared.b16 {%0,%1,%2,%3}, [%4];"
                 : "=r"(r[0]), "=r"(r[1]), "=r"(r[2]), "=r"(r[3]) : "r"(a));
}
__device__ __forceinline__ void mma_f16(float* c, const uint32_t* a,
                                        const uint32_t* b) {
    asm volatile(
        "mma.sync.aligned.m16n8k16.row.col.f32.f16.f16.f32 "
        "{%0,%1,%2,%3}, {%4,%5,%6,%7}, {%8,%9}, {%0,%1,%2,%3};"
        : "+f"(c[0]), "+f"(c[1]), "+f"(c[2]), "+f"(c[3])
        : "r"(a[0]), "r"(a[1]), "r"(a[2]), "r"(a[3]), "r"(b[0]), "r"(b[1]));
}

__device__ __forceinline__ uint32_t packh2(float a, float b) {
    __half2 h = __floats2half2_rn(a, b);
    return *reinterpret_cast<uint32_t*>(&h);
}

// ---------------- prep: one kernel converts GU (interleaved) and D ----------
__global__ void convert_w_kernel(const float* __restrict__ gate_w,
                                 const float* __restrict__ up_w,
                                 const float* __restrict__ down_w) {
    if (blockIdx.x == 0 && threadIdx.x < NEXP) g_counts[threadIdx.x] = 0;
    if (blockIdx.x < GU_BLOCKS) {
        size_t u = (size_t)blockIdx.x * blockDim.x + threadIdx.x;
        size_t o = u * 8;
        size_t gr = o >> 10;
        int k = (int)(o & 1023);
        int e = (int)(gr >> 10);
        int r = (int)(gr & 1023);
        int i = r >> 1;
        const float* src = ((r & 1) ? up_w : gate_w) + ((size_t)e * IDIM + i) * DDIM + k;
        const float4* s4 = (const float4*)src;
        float4 v0 = s4[0], v1 = s4[1];
        ((uint4*)g_GU)[u] = make_uint4(packh2(v0.x, v0.y), packh2(v0.z, v0.w),
                                       packh2(v1.x, v1.y), packh2(v1.z, v1.w));
    } else {
        size_t u = (size_t)(blockIdx.x - GU_BLOCKS) * blockDim.x + threadIdx.x;
        const float4* s4 = (const float4*)down_w + u * 2;
        float4 v0 = s4[0], v1 = s4[1];
        ((uint4*)g_D)[u] = make_uint4(packh2(v0.x, v0.y), packh2(v0.z, v0.w),
                                      packh2(v1.x, v1.y), packh2(v1.z, v1.w));
    }
}

// ---------------- router (also emits fp16 X) --------------------------------
__global__ void router_kernel(const float* __restrict__ x,
                              const float* __restrict__ rw,
                              float* __restrict__ logits_out) {
    __shared__ float xs[DDIM];
    __shared__ float lsh[NEXP];
    const int t = blockIdx.x;
    const int tid = threadIdx.x;

    const float4* xrow = (const float4*)(x + (size_t)t * DDIM);
    float4* xs4 = (float4*)xs;
    for (int i = tid; i < DDIM / 4; i += 128) xs4[i] = xrow[i];
    __syncthreads();

    {
        uint32_t* xo = (uint32_t*)(g_X + (size_t)t * DDIM);
#pragma unroll
        for (int j = 0; j < 4; j++) {
            int u = tid * 4 + j;
            xo[u] = packh2(xs[u * 2], xs[u * 2 + 1]);
        }
    }

    const int e = tid >> 2;
    const int s = tid & 3;
    const float4* w4 = (const float4*)(rw + e * DDIM + s * 256);
    const float4* a4 = (const float4*)(xs + s * 256);
    float acc = 0.f;
#pragma unroll 16
    for (int j = 0; j < 64; j++) {
        float4 a = a4[j], b = w4[j];
        acc += a.x * b.x + a.y * b.y + a.z * b.z + a.w * b.w;
    }
    acc += __shfl_xor_sync(0xffffffffu, acc, 1);
    acc += __shfl_xor_sync(0xffffffffu, acc, 2);
    if (s == 0) lsh[e] = acc;
    __syncthreads();

    if (tid < 32) {
        float lv = lsh[tid];
        if (logits_out) logits_out[(size_t)t * NEXP + tid] = lv;

        float cur = lv;
        float selv[KSEL];
        int   seli[KSEL];
#pragma unroll
        for (int k = 0; k < KSEL; k++) {
            float v = cur;
            int idx = tid;
#pragma unroll
            for (int off = 16; off; off >>= 1) {
                float ov = __shfl_xor_sync(0xffffffffu, v, off);
                int   oi = __shfl_xor_sync(0xffffffffu, idx, off);
                if (ov > v || (ov == v && oi < idx)) { v = ov; idx = oi; }
            }
            selv[k] = v;
            seli[k] = idx;
            if (tid == idx) cur = -3.4e38f;
        }

        if (tid < KSEL) {
            float m = selv[0];
            float sum = 0.f;
#pragma unroll
            for (int k = 0; k < KSEL; k++) sum += expf(selv[k] - m);
            float w = expf(selv[tid] - m) / sum;
            int   ex = seli[tid];
            int p = atomicAdd(&g_counts[ex], 1);
            int o = t * KSEL + tid;
            g_tok_exp[o] = ex;
            g_tok_pos[o] = p;
            g_tok_w[o]   = w;
            if (p < CAP) g_row_token[ex * CAP + p] = t;
        }
    }
}

__global__ void combine_kernel(float* __restrict__ out) {
    const int t = blockIdx.x;
    const int d = threadIdx.x * 4;
    float4 acc = make_float4(0.f, 0.f, 0.f, 0.f);
#pragma unroll
    for (int k = 0; k < KSEL; k++) {
        int o = t * KSEL + k;
        int e = g_tok_exp[o];
        int p = g_tok_pos[o];
        float w = g_tok_w[o];
        if (p < CAP) {
            const __half2* yp = (const __half2*)(g_Yh + ((size_t)e * CAP + p) * DDIM + d);
            float2 v0 = __half22float2(yp[0]);
            float2 v1 = __half22float2(yp[1]);
            acc.x += w * v0.x; acc.y += w * v0.y;
            acc.z += w * v1.x; acc.w += w * v1.y;
        }
    }
    *(float4*)&out[(size_t)t * DDIM + d] = acc;
}

// ---------------- GEMM phase 1: M=256 tile, 3-stage pipeline ----------------
__global__ __launch_bounds__(P1_THREADS)
void phase1_kernel() {
    extern __shared__ char smem[];
    const int e = blockIdx.z;
    const int cnt = min(g_counts[e], CAP);
    const int m0 = blockIdx.y * 256;
    if (m0 >= cnt) return;
    const int x0 = blockIdx.x;          // 64 i-values per tile
    const uint32_t sb = smem_u32(smem);
    int* tok_s = (int*)(smem + 3 * P1_BUF);

    const int tid = threadIdx.x;
    const int lane = tid & 31;
    const int wid = tid >> 5;
    const int wm = wid >> 1;            // 0..7
    const int wn = wid & 1;

    if (tid < 256) {
        int m = m0 + tid;
        tok_s[tid] = (m < cnt) ? g_row_token[e * CAP + m] : 0;
    }
    __syncthreads();

    int mytok[4];
#pragma unroll
    for (int it = 0; it < 4; it++) mytok[it] = tok_s[(tid >> 3) + 64 * it];
    const int myl = tid & 7;

    const size_t bbase = ((size_t)e * 1024 + x0 * 128) * DDIM;

    auto load_chunk = [&](int buf, int c) {
        uint32_t s = sb + buf * P1_BUF;
        int kk = c * 64;
#pragma unroll
        for (int it = 0; it < 4; it++) {             // A: 256 rows
            int row = (tid >> 3) + 64 * it;
            uint32_t dst = s + row * 128 + ((myl ^ (row & 7)) << 4);
            cp_async16(dst, g_X + (size_t)mytok[it] * DDIM + kk + myl * 8);
        }
#pragma unroll
        for (int it = 0; it < 2; it++) {             // B: 128 rows
            int row = (tid >> 3) + 64 * it;
            uint32_t dst = s + P1_A + row * 128 + ((myl ^ (row & 7)) << 4);
            cp_async16(dst, g_GU + bbase + (size_t)row * DDIM + kk + myl * 8);
        }
    };

    float acc[2][8][4] = {};
    const int g = lane >> 3;
    const int ar_off = (lane & 7) + (g & 1) * 8;
    const int ac_off = g >> 1;
    const int br_off = (lane & 7) + (g >> 1) * 8;
    const int bc_off = g & 1;

    load_chunk(0, 0); CP_COMMIT();
    load_chunk(1, 1); CP_COMMIT();
    int buf = 0;
    for (int c = 0; c < 16; c++) {
        if (c + 2 < 16) {
            int nb = buf + 2; if (nb >= 3) nb -= 3;
            load_chunk(nb, c + 2); CP_COMMIT(); CP_WAIT2();
        } else if (c + 1 < 16) CP_WAIT1();
        else CP_WAIT0();
        __syncthreads();
        uint32_t s = sb + buf * P1_BUF;
#pragma unroll
        for (int h = 0; h < 4; h++) {
            uint32_t ah[2][4], bb[4][4];
#pragma unroll
            for (int t = 0; t < 2; t++) {
                int r = wm * 32 + t * 16 + ar_off;
                int cc = h * 2 + ac_off;
                ldsm4(ah[t], s + r * 128 + ((cc ^ (r & 7)) << 4));
            }
#pragma unroll
            for (int j2 = 0; j2 < 4; j2++) {
                int n = wn * 64 + j2 * 16 + br_off;
                int cc = h * 2 + bc_off;
                ldsm4(bb[j2], s + P1_A + n * 128 + ((cc ^ (n & 7)) << 4));
            }
#pragma unroll
            for (int t = 0; t < 2; t++)
#pragma unroll
                for (int j = 0; j < 8; j++)
                    mma_f16(acc[t][j], ah[t], &bb[j >> 1][(j & 1) * 2]);
        }
        __syncthreads();
        if (++buf == 3) buf = 0;
    }

    // epilogue: c0 = gate_i, c1 = up_i (row-interleaved B) -> h = silu(g)*u
#pragma unroll
    for (int t = 0; t < 2; t++)
#pragma unroll
        for (int rh = 0; rh < 2; rh++) {
            int m = m0 + wm * 32 + t * 16 + rh * 8 + (lane >> 2);
            if (m < cnt) {
                size_t base = ((size_t)e * CAP + m) * IDIM + x0 * 64 + wn * 32 + (lane & 3);
#pragma unroll
                for (int j = 0; j < 8; j++) {
                    float gg = acc[t][j][rh * 2];
                    float uu = acc[t][j][rh * 2 + 1];
                    float hh = gg * (1.f / (1.f + expf(-gg))) * uu;
                    g_H[base + j * 4] = __float2half_rn(hh);
                }
            }
        }
}

// ---------------- GEMM phase 2: M=128 tile, 256 thr, 2-stage, fp16 out -----
__global__ __launch_bounds__(P2_THREADS)
void phase2_kernel() {
    extern __shared__ char smem[];
    const int e = blockIdx.z;
    const int cnt = min(g_counts[e], CAP);
    const int m0 = blockIdx.y * 128;
    if (m0 >= cnt) return;
    const int d0 = blockIdx.x * 128;
    const uint32_t sb = smem_u32(smem);

    const int tid = threadIdx.x;
    const int lane = tid & 31;
    const int wid = tid >> 5;
    const int wm = wid >> 1;
    const int wn = wid & 1;
    const int mycc = tid & 7;

    const size_t abase = ((size_t)e * CAP + m0) * IDIM;
    const size_t bbase = ((size_t)e * DDIM + d0) * IDIM;

    auto load_chunk = [&](int buf, int c) {
        uint32_t s = sb + buf * P2_BUF;
        int kk = c * 64;
#pragma unroll
        for (int it = 0; it < 4; it++) {
            int row = (tid >> 3) + 32 * it;
            uint32_t dst = s + row * 128 + ((mycc ^ (row & 7)) << 4);
            cp_async16(dst,        g_H + abase + (size_t)row * IDIM + kk + mycc * 8);
            cp_async16(dst + P2_T, g_D + bbase + (size_t)row * IDIM + kk + mycc * 8);
        }
    };

    float acc[2][8][4] = {};
    const int g = lane >> 3;
    const int ar_off = (lane & 7) + (g & 1) * 8;
    const int ac_off = g >> 1;
    const int br_off = (lane & 7) + (g >> 1) * 8;
    const int bc_off = g & 1;

    load_chunk(0, 0); CP_COMMIT();
    for (int c = 0; c < 8; c++) {
        if (c + 1 < 8) { load_chunk((c + 1) & 1, c + 1); CP_COMMIT(); CP_WAIT1(); }
        else CP_WAIT0();
        __syncthreads();
        uint32_t s = sb + (c & 1) * P2_BUF;
#pragma unroll
        for (int h = 0; h < 4; h++) {
            uint32_t ah[2][4], bb[4][4];
#pragma unroll
            for (int t = 0; t < 2; t++) {
                int r = wm * 32 + t * 16 + ar_off;
                int cc = h * 2 + ac_off;
                ldsm4(ah[t], s + r * 128 + ((cc ^ (r & 7)) << 4));
            }
#pragma unroll
            for (int j2 = 0; j2 < 4; j2++) {
                int n = wn * 64 + j2 * 16 + br_off;
                int cc = h * 2 + bc_off;
                ldsm4(bb[j2], s + P2_T + n * 128 + ((cc ^ (n & 7)) << 4));
            }
#pragma unroll
            for (int t = 0; t < 2; t++)
#pragma unroll
                for (int j = 0; j < 8; j++)
                    mma_f16(acc[t][j], ah[t], &bb[j >> 1][(j & 1) * 2]);
        }
        __syncthreads();
    }

#pragma unroll
    for (int t = 0; t < 2; t++)
#pragma unroll
        for (int rh = 0; rh < 2; rh++) {
            int m = m0 + wm * 32 + t * 16 + rh * 8 + (lane >> 2);
            if (m < cnt) {
                __half* yp = g_Yh + ((size_t)e * CAP + m) * DDIM
                           + d0 + wn * 64 + (lane & 3) * 2;
#pragma unroll
                for (int j = 0; j < 8; j++) {
                    *(uint32_t*)(yp + j * 8) =
                        packh2(acc[t][j][rh * 2], acc[t][j][rh * 2 + 1]);
                }
            }
        }
}

// ---------------- host ------------------------------------------------------
extern "C" void kernel_launch(void* const* d_in, const int* in_sizes, int n_in,
                              void* d_out, int out_size) {
    const float* x  = (const float*)d_in[0];
    const float* rw = (const float*)d_in[1];
    const float* gw = (const float*)d_in[2];
    const float* uw = (const float*)d_in[3];
    const float* dw = (const float*)d_in[4];
    float* out = (float*)d_out;
    float* logits = (out_size >= NTOK * DDIM + NTOK * NEXP) ? (out + (size_t)NTOK * DDIM)
                                                            : nullptr;

    cudaFuncSetAttribute(phase1_kernel, cudaFuncAttributeMaxDynamicSharedMemorySize, SMEM_P1);
    cudaFuncSetAttribute(phase2_kernel, cudaFuncAttributeMaxDynamicSharedMemorySize, SMEM_P2);

    convert_w_kernel<<<GU_BLOCKS + D_BLOCKS, 256>>>(gw, uw, dw);
    router_kernel<<<NTOK, 128>>>(x, rw, logits);
    phase1_kernel<<<dim3(IDIM / 64, CAP / 256, NEXP), P1_THREADS, SMEM_P1>>>();
    phase2_kernel<<<dim3(DDIM / 128, CAP / 128, NEXP), P2_THREADS, SMEM_P2>>>();
    combine_kernel<<<NTOK, 256>>>(out);
}

// round 17
// speedup vs baseline: 1.0970x; 1.0627x over previous
#include <cuda_runtime.h>
#include <cuda_fp16.h>
#include <math.h>
#include <stdint.h>

#define NEXP 32
#define KSEL 4
#define CAP  1280
#define NTOK 8192
#define DDIM 1024
#define IDIM 512

// phase1: M=256 tile, 512 threads, 3-stage
#define P1_THREADS 512
#define P1_A  32768
#define P1_B  16384
#define P1_BUF (P1_A + P1_B)
#define SMEM_P1 (3 * P1_BUF + 1024)
// phase2: M=128 tile, 256 threads, 2-stage
#define P2_THREADS 256
#define P2_T  16384
#define P2_BUF (2 * P2_T)
#define SMEM_P2 (2 * P2_BUF + 1024)
// router: 16 tokens/block, rw cached in smem
#define RT_TB 16
#define SMEM_RT (131072 + 65536 + 2048)

#define GU_BLOCKS (NEXP * 1024 * DDIM / 8 / 256)   // 16384
#define D_BLOCKS  (NEXP * DDIM * IDIM / 8 / 256)   // 8192

// ---------------- scratch (device globals; no allocation allowed) ----------
__device__ int   g_counts[NEXP];
__device__ int   g_row_token[NEXP * CAP];
__device__ int   g_tok_exp[NTOK * KSEL];
__device__ int   g_tok_pos[NTOK * KSEL];
__device__ float g_tok_w[NTOK * KSEL];

__device__ __half g_X [(size_t)NTOK * DDIM];
__device__ __half g_GU[(size_t)NEXP * 1024 * DDIM];   // gate/up row-interleaved
__device__ __half g_D [(size_t)NEXP * DDIM * IDIM];
__device__ __half g_H [(size_t)NEXP * CAP * IDIM];
__device__ __half g_Yh[(size_t)NEXP * CAP * DDIM];

// ---------------- PTX helpers (base compute_103 target only) ---------------
__device__ __forceinline__ uint32_t smem_u32(const void* p) {
    uint32_t a;
    asm("{ .reg .u64 t; cvta.to.shared.u64 t, %1; cvt.u32.u64 %0, t; }"
        : "=r"(a) : "l"(p));
    return a;
}
__device__ __forceinline__ void cp_async16(uint32_t dst, const void* src) {
    asm volatile("cp.async.cg.shared.global [%0], [%1], 16;"
                 :: "r"(dst), "l"(src));
}
#define CP_COMMIT() asm volatile("cp.async.commit_group;" ::: "memory")
#define CP_WAIT2()  asm volatile("cp.async.wait_group 2;" ::: "memory")
#define CP_WAIT1()  asm volatile("cp.async.wait_group 1;" ::: "memory")
#define CP_WAIT0()  asm volatile("cp.async.wait_group 0;" ::: "memory")

__device__ __forceinline__ void ldsm4(uint32_t* r, uint32_t a) {
    asm volatile("ldmatrix.sync.aligned.m8n8.x4.shared.b16 {%0,%1,%2,%3}, [%4];"
                 : "=r"(r[0]), "=r"(r[1]), "=r"(r[2]), "=r"(r[3]) : "r"(a));
}
__device__ __forceinline__ void mma_f16(float* c, const uint32_t* a,
                                        const uint32_t* b) {
    asm volatile(
        "mma.sync.aligned.m16n8k16.row.col.f32.f16.f16.f32 "
        "{%0,%1,%2,%3}, {%4,%5,%6,%7}, {%8,%9}, {%0,%1,%2,%3};"
        : "+f"(c[0]), "+f"(c[1]), "+f"(c[2]), "+f"(c[3])
        : "r"(a[0]), "r"(a[1]), "r"(a[2]), "r"(a[3]), "r"(b[0]), "r"(b[1]));
}

__device__ __forceinline__ uint32_t packh2(float a, float b) {
    __half2 h = __floats2half2_rn(a, b);
    return *reinterpret_cast<uint32_t*>(&h);
}

// ---------------- prep: one kernel converts GU (interleaved) and D ----------
__global__ void convert_w_kernel(const float* __restrict__ gate_w,
                                 const float* __restrict__ up_w,
                                 const float* __restrict__ down_w) {
    if (blockIdx.x == 0 && threadIdx.x < NEXP) g_counts[threadIdx.x] = 0;
    if (blockIdx.x < GU_BLOCKS) {
        size_t u = (size_t)blockIdx.x * blockDim.x + threadIdx.x;
        size_t o = u * 8;
        size_t gr = o >> 10;
        int k = (int)(o & 1023);
        int e = (int)(gr >> 10);
        int r = (int)(gr & 1023);
        int i = r >> 1;
        const float* src = ((r & 1) ? up_w : gate_w) + ((size_t)e * IDIM + i) * DDIM + k;
        const float4* s4 = (const float4*)src;
        float4 v0 = s4[0], v1 = s4[1];
        ((uint4*)g_GU)[u] = make_uint4(packh2(v0.x, v0.y), packh2(v0.z, v0.w),
                                       packh2(v1.x, v1.y), packh2(v1.z, v1.w));
    } else {
        size_t u = (size_t)(blockIdx.x - GU_BLOCKS) * blockDim.x + threadIdx.x;
        const float4* s4 = (const float4*)down_w + u * 2;
        float4 v0 = s4[0], v1 = s4[1];
        ((uint4*)g_D)[u] = make_uint4(packh2(v0.x, v0.y), packh2(v0.z, v0.w),
                                      packh2(v1.x, v1.y), packh2(v1.z, v1.w));
    }
}

// ---------------- router: 16 tokens/block, rw cached in smem ----------------
__global__ __launch_bounds__(256)
void router_kernel(const float* __restrict__ x,
                   const float* __restrict__ rw,
                   float* __restrict__ logits_out) {
    extern __shared__ float sm[];
    float* rws = sm;                    // 32768 floats
    float* xs  = sm + 32768;            // 16384 floats (16 token rows)
    float* lsh = sm + 49152;            // 512 floats (16 x 32 logits)
    const int tid = threadIdx.x;
    const int t0 = blockIdx.x * RT_TB;

    float4* rw4 = (float4*)rws;
#pragma unroll
    for (int j = 0; j < 32; j++) rw4[tid + 256 * j] = ((const float4*)rw)[tid + 256 * j];
    float4* xs4 = (float4*)xs;
#pragma unroll
    for (int j = 0; j < 16; j++) {
        int u = tid + 256 * j;          // u < 4096; token = u>>8, f4 = u&255
        xs4[u] = ((const float4*)(x + (size_t)(t0 + (u >> 8)) * DDIM))[u & 255];
    }
    __syncthreads();

    // emit fp16 X copy
#pragma unroll
    for (int j = 0; j < 32; j++) {
        int u = tid + 256 * j;          // u < 8192 (16 tokens x 512 half2)
        int tt = u >> 9, off = u & 511;
        ((uint32_t*)(g_X + (size_t)(t0 + tt) * DDIM))[off] =
            packh2(xs[tt * 1024 + off * 2], xs[tt * 1024 + off * 2 + 1]);
    }

    // logits: 8 threads per expert, 128-wide chunks
    const int e = tid >> 3, s = tid & 7;
    const float4* rr = (const float4*)rws + e * 256 + s * 32;
    for (int t = 0; t < RT_TB; t++) {
        const float4* xx = (const float4*)xs + t * 256 + s * 32;
        float acc = 0.f;
#pragma unroll
        for (int j = 0; j < 32; j++) {
            float4 a = xx[j], b = rr[j];
            acc += a.x * b.x + a.y * b.y + a.z * b.z + a.w * b.w;
        }
        acc += __shfl_xor_sync(0xffffffffu, acc, 1);
        acc += __shfl_xor_sync(0xffffffffu, acc, 2);
        acc += __shfl_xor_sync(0xffffffffu, acc, 4);
        if (s == 0) lsh[t * 32 + e] = acc;
    }
    __syncthreads();

    // top-k: warp w handles tokens 2w, 2w+1
    const int wid = tid >> 5, lane = tid & 31;
    for (int ti = 0; ti < 2; ti++) {
        int t = wid * 2 + ti;
        int tok = t0 + t;
        float lv = lsh[t * 32 + lane];
        if (logits_out) logits_out[(size_t)tok * NEXP + lane] = lv;

        float cur = lv;
        float selv[KSEL];
        int   seli[KSEL];
#pragma unroll
        for (int k = 0; k < KSEL; k++) {
            float v = cur;
            int idx = lane;
#pragma unroll
            for (int off = 16; off; off >>= 1) {
                float ov = __shfl_xor_sync(0xffffffffu, v, off);
                int   oi = __shfl_xor_sync(0xffffffffu, idx, off);
                if (ov > v || (ov == v && oi < idx)) { v = ov; idx = oi; }
            }
            selv[k] = v;
            seli[k] = idx;
            if (lane == idx) cur = -3.4e38f;
        }

        if (lane < KSEL) {
            float m = selv[0];
            float sum = 0.f;
#pragma unroll
            for (int k = 0; k < KSEL; k++) sum += expf(selv[k] - m);
            float w = expf(selv[lane] - m) / sum;
            int   ex = seli[lane];
            int p = atomicAdd(&g_counts[ex], 1);
            int o = tok * KSEL + lane;
            g_tok_exp[o] = ex;
            g_tok_pos[o] = p;
            g_tok_w[o]   = w;
            if (p < CAP) g_row_token[ex * CAP + p] = tok;
        }
    }
}

__global__ void combine_kernel(float* __restrict__ out) {
    const int t = blockIdx.x;
    const int d = threadIdx.x * 4;
    float4 acc = make_float4(0.f, 0.f, 0.f, 0.f);
#pragma unroll
    for (int k = 0; k < KSEL; k++) {
        int o = t * KSEL + k;
        int e = g_tok_exp[o];
        int p = g_tok_pos[o];
        float w = g_tok_w[o];
        if (p < CAP) {
            const __half2* yp = (const __half2*)(g_Yh + ((size_t)e * CAP + p) * DDIM + d);
            float2 v0 = __half22float2(yp[0]);
            float2 v1 = __half22float2(yp[1]);
            acc.x += w * v0.x; acc.y += w * v0.y;
            acc.z += w * v1.x; acc.w += w * v1.y;
        }
    }
    *(float4*)&out[(size_t)t * DDIM + d] = acc;
}

// ---------------- GEMM phase 1: M=256 tile, 3-stage pipeline ----------------
__global__ __launch_bounds__(P1_THREADS)
void phase1_kernel() {
    extern __shared__ char smem[];
    const int e = blockIdx.z;
    const int cnt = min(g_counts[e], CAP);
    const int m0 = blockIdx.y * 256;
    if (m0 >= cnt) return;
    const int x0 = blockIdx.x;
    const uint32_t sb = smem_u32(smem);
    int* tok_s = (int*)(smem + 3 * P1_BUF);

    const int tid = threadIdx.x;
    const int lane = tid & 31;
    const int wid = tid >> 5;
    const int wm = wid >> 1;
    const int wn = wid & 1;

    if (tid < 256) {
        int m = m0 + tid;
        tok_s[tid] = (m < cnt) ? g_row_token[e * CAP + m] : 0;
    }
    __syncthreads();

    int mytok[4];
#pragma unroll
    for (int it = 0; it < 4; it++) mytok[it] = tok_s[(tid >> 3) + 64 * it];
    const int myl = tid & 7;

    const size_t bbase = ((size_t)e * 1024 + x0 * 128) * DDIM;

    auto load_chunk = [&](int buf, int c) {
        uint32_t s = sb + buf * P1_BUF;
        int kk = c * 64;
#pragma unroll
        for (int it = 0; it < 4; it++) {
            int row = (tid >> 3) + 64 * it;
            uint32_t dst = s + row * 128 + ((myl ^ (row & 7)) << 4);
            cp_async16(dst, g_X + (size_t)mytok[it] * DDIM + kk + myl * 8);
        }
#pragma unroll
        for (int it = 0; it < 2; it++) {
            int row = (tid >> 3) + 64 * it;
            uint32_t dst = s + P1_A + row * 128 + ((myl ^ (row & 7)) << 4);
            cp_async16(dst, g_GU + bbase + (size_t)row * DDIM + kk + myl * 8);
        }
    };

    float acc[2][8][4] = {};
    const int g = lane >> 3;
    const int ar_off = (lane & 7) + (g & 1) * 8;
    const int ac_off = g >> 1;
    const int br_off = (lane & 7) + (g >> 1) * 8;
    const int bc_off = g & 1;

    load_chunk(0, 0); CP_COMMIT();
    load_chunk(1, 1); CP_COMMIT();
    int buf = 0;
    for (int c = 0; c < 16; c++) {
        if (c + 2 < 16) {
            int nb = buf + 2; if (nb >= 3) nb -= 3;
            load_chunk(nb, c + 2); CP_COMMIT(); CP_WAIT2();
        } else if (c + 1 < 16) CP_WAIT1();
        else CP_WAIT0();
        __syncthreads();
        uint32_t s = sb + buf * P1_BUF;
#pragma unroll
        for (int h = 0; h < 4; h++) {
            uint32_t ah[2][4], bb[4][4];
#pragma unroll
            for (int t = 0; t < 2; t++) {
                int r = wm * 32 + t * 16 + ar_off;
                int cc = h * 2 + ac_off;
                ldsm4(ah[t], s + r * 128 + ((cc ^ (r & 7)) << 4));
            }
#pragma unroll
            for (int j2 = 0; j2 < 4; j2++) {
                int n = wn * 64 + j2 * 16 + br_off;
                int cc = h * 2 + bc_off;
                ldsm4(bb[j2], s + P1_A + n * 128 + ((cc ^ (n & 7)) << 4));
            }
#pragma unroll
            for (int t = 0; t < 2; t++)
#pragma unroll
                for (int j = 0; j < 8; j++)
                    mma_f16(acc[t][j], ah[t], &bb[j >> 1][(j & 1) * 2]);
        }
        __syncthreads();
        if (++buf == 3) buf = 0;
    }

    // epilogue: SwiGLU, stage to smem, coalesced store (256 rows x 64 cols)
    __half* hs = (__half*)smem;
#pragma unroll
    for (int t = 0; t < 2; t++)
#pragma unroll
        for (int rh = 0; rh < 2; rh++) {
            int r = wm * 32 + t * 16 + rh * 8 + (lane >> 2);
#pragma unroll
            for (int j = 0; j < 8; j++) {
                float gg = acc[t][j][rh * 2];
                float uu = acc[t][j][rh * 2 + 1];
                float hh = gg * (1.f / (1.f + expf(-gg))) * uu;
                hs[r * 64 + wn * 32 + (lane & 3) + j * 4] = __float2half_rn(hh);
            }
        }
    __syncthreads();
#pragma unroll
    for (int q = 0; q < 4; q++) {
        int unit = tid + P1_THREADS * q;   // 2048 uint4 units
        int r = unit >> 3;
        int cc = unit & 7;
        if (m0 + r < cnt)
            *(uint4*)(g_H + ((size_t)e * CAP + m0 + r) * IDIM + x0 * 64 + cc * 8) =
                ((const uint4*)hs)[unit];
    }
}

// ---------------- GEMM phase 2: M=128 tile, 256 thr, 2-stage, fp16 out -----
__global__ __launch_bounds__(P2_THREADS)
void phase2_kernel() {
    extern __shared__ char smem[];
    const int e = blockIdx.z;
    const int cnt = min(g_counts[e], CAP);
    const int m0 = blockIdx.y * 128;
    if (m0 >= cnt) return;
    const int d0 = blockIdx.x * 128;
    const uint32_t sb = smem_u32(smem);

    const int tid = threadIdx.x;
    const int lane = tid & 31;
    const int wid = tid >> 5;
    const int wm = wid >> 1;
    const int wn = wid & 1;
    const int mycc = tid & 7;

    const size_t abase = ((size_t)e * CAP + m0) * IDIM;
    const size_t bbase = ((size_t)e * DDIM + d0) * IDIM;

    auto load_chunk = [&](int buf, int c) {
        uint32_t s = sb + buf * P2_BUF;
        int kk = c * 64;
#pragma unroll
        for (int it = 0; it < 4; it++) {
            int row = (tid >> 3) + 32 * it;
            uint32_t dst = s + row * 128 + ((mycc ^ (row & 7)) << 4);
            cp_async16(dst,        g_H + abase + (size_t)row * IDIM + kk + mycc * 8);
            cp_async16(dst + P2_T, g_D + bbase + (size_t)row * IDIM + kk + mycc * 8);
        }
    };

    float acc[2][8][4] = {};
    const int g = lane >> 3;
    const int ar_off = (lane & 7) + (g & 1) * 8;
    const int ac_off = g >> 1;
    const int br_off = (lane & 7) + (g >> 1) * 8;
    const int bc_off = g & 1;

    load_chunk(0, 0); CP_COMMIT();
    for (int c = 0; c < 8; c++) {
        if (c + 1 < 8) { load_chunk((c + 1) & 1, c + 1); CP_COMMIT(); CP_WAIT1(); }
        else CP_WAIT0();
        __syncthreads();
        uint32_t s = sb + (c & 1) * P2_BUF;
#pragma unroll
        for (int h = 0; h < 4; h++) {
            uint32_t ah[2][4], bb[4][4];
#pragma unroll
            for (int t = 0; t < 2; t++) {
                int r = wm * 32 + t * 16 + ar_off;
                int cc = h * 2 + ac_off;
                ldsm4(ah[t], s + r * 128 + ((cc ^ (r & 7)) << 4));
            }
#pragma unroll
            for (int j2 = 0; j2 < 4; j2++) {
                int n = wn * 64 + j2 * 16 + br_off;
                int cc = h * 2 + bc_off;
                ldsm4(bb[j2], s + P2_T + n * 128 + ((cc ^ (n & 7)) << 4));
            }
#pragma unroll
            for (int t = 0; t < 2; t++)
#pragma unroll
                for (int j = 0; j < 8; j++)
                    mma_f16(acc[t][j], ah[t], &bb[j >> 1][(j & 1) * 2]);
        }
        __syncthreads();
    }

    // epilogue: stage 128x128 fp16 tile in smem, coalesced store
    __half* hs = (__half*)smem;
#pragma unroll
    for (int t = 0; t < 2; t++)
#pragma unroll
        for (int rh = 0; rh < 2; rh++) {
            int r = wm * 32 + t * 16 + rh * 8 + (lane >> 2);
#pragma unroll
            for (int j = 0; j < 8; j++) {
                *(uint32_t*)(hs + r * 128 + wn * 64 + (lane & 3) * 2 + j * 8) =
                    packh2(acc[t][j][rh * 2], acc[t][j][rh * 2 + 1]);
            }
        }
    __syncthreads();
#pragma unroll
    for (int q = 0; q < 8; q++) {
        int unit = tid + P2_THREADS * q;   // 2048 uint4 units
        int r = unit >> 4;
        int cc = unit & 15;
        if (m0 + r < cnt)
            *(uint4*)(g_Yh + ((size_t)e * CAP + m0 + r) * DDIM + d0 + cc * 8) =
                ((const uint4*)hs)[unit];
    }
}

// ---------------- host ------------------------------------------------------
extern "C" void kernel_launch(void* const* d_in, const int* in_sizes, int n_in,
                              void* d_out, int out_size) {
    const float* x  = (const float*)d_in[0];
    const float* rw = (const float*)d_in[1];
    const float* gw = (const float*)d_in[2];
    const float* uw = (const float*)d_in[3];
    const float* dw = (const float*)d_in[4];
    float* out = (float*)d_out;
    float* logits = (out_size >= NTOK * DDIM + NTOK * NEXP) ? (out + (size_t)NTOK * DDIM)
                                                            : nullptr;

    cudaFuncSetAttribute(phase1_kernel, cudaFuncAttributeMaxDynamicSharedMemorySize, SMEM_P1);
    cudaFuncSetAttribute(phase2_kernel, cudaFuncAttributeMaxDynamicSharedMemorySize, SMEM_P2);
    cudaFuncSetAttribute(router_kernel, cudaFuncAttributeMaxDynamicSharedMemorySize, SMEM_RT);

    convert_w_kernel<<<GU_BLOCKS + D_BLOCKS, 256>>>(gw, uw, dw);
    router_kernel<<<NTOK / RT_TB, 256, SMEM_RT>>>(x, rw, logits);
    phase1_kernel<<<dim3(IDIM / 64, CAP / 256, NEXP), P1_THREADS, SMEM_P1>>>();
    phase2_kernel<<<dim3(DDIM / 128, CAP / 128, NEXP), P2_THREADS, SMEM_P2>>>();
    combine_kernel<<<NTOK, 256>>>(out);
}